// round 16
// baseline (speedup 1.0000x reference)
#include <cuda_runtime.h>
#include <cuda_fp16.h>
#include <stdint.h>
#include <math.h>

// Problem dims (fixed by reference)
#define BB   128          // batch
#define TT   1024         // tokens
#define HH   512          // hidden
#define AA   256          // attention dim
#define GG   2128         // genes

#define NSTAGE 16         // K stages
#define KC     32         // K per stage
#define LDAF   260        // A smem row stride in b32 words (256 data + 4 pad)
#define LDB    20         // B smem row stride in b32 words
#define NTILE  (TT / 128) // 8 token tiles per batch
#define GSPLIT 16
#define GCHUNK 133        // GG / 16
#define BROWS  8          // batch rows per gene CTA

// smem word layout for attn kernel:
//   A resident: [0, 128*260) = [0, 33280)
//   Bs[buf] at 33280 + buf*5120, buf=0,1 -> ends 43520
//   comb @43520, v @43776, part @44032 (4x128) -> 44544
//   lg @44544 (128), ew @44672 (128), scal @44800 (4), pn @44816 (1024)
#define BBASE_W 33280u
#define COMB_W  43520u
#define VSH_W   43776u
#define PART_W  44032u
#define LG_W    44544u
#define EW_W    44672u
#define SCAL_W  44800u
#define PN_W    44816u
#define SMEM_BYTES ((PN_W + 1024u) * 4u)   // 183360 B

// ---------------- scratch (no cudaMalloc allowed) ----------------
__device__ float    g_gp_part[GSPLIT * BB * AA];     // gene partials
__device__ float    g_logits[BB * TT];               // pre-softmax energies
__device__ __align__(16) unsigned g_bh[NSTAGE * AA * (KC / 2)]; // dkernel^T fp16
__device__ float    g_ms[BB * NTILE * 2];            // per-tile (max, expsum)
__device__ float    g_pnum[BB * NTILE * HH];         // per-tile weighted-sum numerators

// ---------------- helpers ----------------
__device__ __forceinline__ unsigned packh2(float a, float b) {
    __half2 h = __floats2half2_rn(a, b);              // low = a, high = b
    return *reinterpret_cast<unsigned*>(&h);
}
__device__ __forceinline__ uint32_t s2u(const void* p) {
    uint32_t a;
    asm("{ .reg .u64 t; cvta.to.shared.u64 t, %1; cvt.u32.u64 %0, t; }" : "=r"(a) : "l"(p));
    return a;
}
__device__ __forceinline__ void cp16(uint32_t d, const void* s) {
    asm volatile("cp.async.cg.shared.global [%0], [%1], 16;" :: "r"(d), "l"(s) : "memory");
}
__device__ __forceinline__ void ldmat4(unsigned* r, uint32_t addr) {
    asm volatile("ldmatrix.sync.aligned.m8n8.x4.shared.b16 {%0,%1,%2,%3}, [%4];"
                 : "=r"(r[0]), "=r"(r[1]), "=r"(r[2]), "=r"(r[3]) : "r"(addr));
}
__device__ __forceinline__ void mma_f16(float& d0, float& d1, float& d2, float& d3,
                                        unsigned a0, unsigned a1, unsigned a2, unsigned a3,
                                        unsigned b0, unsigned b1) {
    asm volatile(
        "mma.sync.aligned.m16n8k16.row.col.f32.f16.f16.f32 "
        "{%0,%1,%2,%3}, {%4,%5,%6,%7}, {%8,%9}, {%0,%1,%2,%3};\n"
        : "+f"(d0), "+f"(d1), "+f"(d2), "+f"(d3)
        : "r"(a0), "r"(a1), "r"(a2), "r"(a3), "r"(b0), "r"(b1));
}

// ================= Kernel A: gene partials (y<16, 8 b-rows/CTA) + B prep (y==16) =================
__global__ __launch_bounds__(256) void gene_and_prep(
    const float* __restrict__ genes,
    const float* __restrict__ w_genes,
    const float* __restrict__ dk)
{
    const int tid = threadIdx.x;

    if (blockIdx.y == GSPLIT) {
        // ---- prep B: dkernel^T -> fp16, stage-blocked (x = stage, 16 blocks) ----
        const int s = blockIdx.x;
        const int a = tid;
        unsigned w[16];
        #pragma unroll
        for (int j = 0; j < 16; j++) {
            float f0 = dk[(size_t)(s * KC + 2 * j)     * AA + a];
            float f1 = dk[(size_t)(s * KC + 2 * j + 1) * AA + a];
            w[j] = packh2(f0, f1);
        }
        uint4* dst = reinterpret_cast<uint4*>(g_bh + ((size_t)s * AA + a) * 16);
        dst[0] = make_uint4(w[0],  w[1],  w[2],  w[3]);
        dst[1] = make_uint4(w[4],  w[5],  w[6],  w[7]);
        dst[2] = make_uint4(w[8],  w[9],  w[10], w[11]);
        dst[3] = make_uint4(w[12], w[13], w[14], w[15]);
        return;
    }

    // ---- gene projection partials (G split 16-way, 8 b-rows, MLP 8) ----
    __shared__ __align__(16) float gs[BROWS * GCHUNK];   // transposed: gs[g*8 + bb]
    const int b0  = blockIdx.x * BROWS;
    const int g0  = blockIdx.y * GCHUNK;

    for (int idx = tid; idx < BROWS * GCHUNK; idx += 256) {
        int bb = idx / GCHUNK;
        int g  = idx - bb * GCHUNK;
        gs[g * BROWS + bb] = genes[(b0 + bb) * GG + g0 + g];
    }
    __syncthreads();

    const int a = tid;
    const float* wp = w_genes + (size_t)g0 * AA + a;
    float acc[BROWS];
    #pragma unroll
    for (int e = 0; e < BROWS; e++) acc[e] = 0.f;

    int g = 0;
    #pragma unroll 1
    for (; g + 8 <= GCHUNK; g += 8) {
        float w[8];
        #pragma unroll
        for (int k = 0; k < 8; k++) w[k] = __ldg(wp + (size_t)(g + k) * AA);
        #pragma unroll
        for (int k = 0; k < 8; k++) {
            float4 gv0 = *reinterpret_cast<const float4*>(&gs[(g + k) * BROWS]);
            float4 gv1 = *reinterpret_cast<const float4*>(&gs[(g + k) * BROWS + 4]);
            acc[0] = fmaf(gv0.x, w[k], acc[0]);
            acc[1] = fmaf(gv0.y, w[k], acc[1]);
            acc[2] = fmaf(gv0.z, w[k], acc[2]);
            acc[3] = fmaf(gv0.w, w[k], acc[3]);
            acc[4] = fmaf(gv1.x, w[k], acc[4]);
            acc[5] = fmaf(gv1.y, w[k], acc[5]);
            acc[6] = fmaf(gv1.z, w[k], acc[6]);
            acc[7] = fmaf(gv1.w, w[k], acc[7]);
        }
    }
    for (; g < GCHUNK; g++) {
        float w = __ldg(wp + (size_t)g * AA);
        float4 gv0 = *reinterpret_cast<const float4*>(&gs[g * BROWS]);
        float4 gv1 = *reinterpret_cast<const float4*>(&gs[g * BROWS + 4]);
        acc[0] = fmaf(gv0.x, w, acc[0]);
        acc[1] = fmaf(gv0.y, w, acc[1]);
        acc[2] = fmaf(gv0.z, w, acc[2]);
        acc[3] = fmaf(gv0.w, w, acc[3]);
        acc[4] = fmaf(gv1.x, w, acc[4]);
        acc[5] = fmaf(gv1.y, w, acc[5]);
        acc[6] = fmaf(gv1.z, w, acc[6]);
        acc[7] = fmaf(gv1.w, w, acc[7]);
    }
    float* dst = g_gp_part + ((size_t)blockIdx.y * BB + b0) * AA + a;
    #pragma unroll
    for (int e = 0; e < BROWS; e++) dst[e * AA] = acc[e];
}

// ================= Kernel B: logits + flash epilogue; A-resident, pipelined fill =================
#define CPB(u) do {                                                              \
    int _buf = (u) & 1;                                                          \
    const char* _s = (const char*)g_bh + (size_t)(u) * 16384;                    \
    uint32_t _d = smb + (BBASE_W + (unsigned)_buf * 5120u) * 4u;                 \
    _Pragma("unroll")                                                            \
    for (int _i = 0; _i < 2; _i++) {                                             \
        int _q = tid + _i * 512;                                                 \
        int _row = _q >> 2, _c = _q & 3;                                         \
        cp16(_d + _row * 80 + _c * 16, _s + _row * 64 + _c * 16);                \
    }                                                                            \
    asm volatile("cp.async.commit_group;" ::: "memory");                         \
} while (0)

#define LDA_G(u, dst) do {                                                       \
    const float* _p = Ag + (size_t)r * HH + (u) * KC + c4 * 8;                   \
    float4 _f0 = *(const float4*)_p;                                             \
    float4 _f1 = *(const float4*)(_p + 4);                                       \
    dst[0] = packh2(_f0.x, _f0.y); dst[1] = packh2(_f0.z, _f0.w);                \
    dst[2] = packh2(_f1.x, _f1.y); dst[3] = packh2(_f1.z, _f1.w);                \
} while (0)

#define STA_RES(u, src) do {                                                     \
    unsigned* _d = smw + r * LDAF + (u) * 16 + c4 * 4;                           \
    *(uint4*)_d = make_uint4(src[0], src[1], src[2], src[3]);                    \
} while (0)

__global__ __launch_bounds__(512, 1) void attn_logits_flash(
    const float* __restrict__ smiles,
    const float* __restrict__ w_num,
    const float* __restrict__ b_genes,
    const float* __restrict__ dbias,
    const float* __restrict__ vvec)
{
    extern __shared__ __align__(16) float sm[];
    unsigned* smw  = (unsigned*)sm;
    float*    comb = sm + COMB_W;
    float*    vsh  = sm + VSH_W;
    float*    part = sm + PART_W;
    float*    lg   = sm + LG_W;
    float*    ew   = sm + EW_W;
    float*    scal = sm + SCAL_W;
    float*    pn   = sm + PN_W;

    const int tid  = threadIdx.x;
    const int lane = tid & 31;
    const int warp = tid >> 5;
    const int g    = lane >> 2;
    const int t4   = lane & 3;
    const int wm   = warp & 3;
    const int wn   = warp >> 2;
    const int b    = blockIdx.y;
    const int t0   = blockIdx.x * 128;

    // fused gene_proj reduce: comb = sum(partials)*w_num + b_genes + dbias
    if (tid < AA) {
        float s = 0.f;
        #pragma unroll
        for (int c = 0; c < GSPLIT; c++) s += g_gp_part[((size_t)c * BB + b) * AA + tid];
        comb[tid] = s * w_num[0] + b_genes[tid] + dbias[tid];
        vsh[tid]  = vvec[tid];
    }

    const float* Ag = smiles + ((size_t)b * TT + t0) * HH;
    const int r  = tid >> 2;          // 0..127 (token row)
    const int c4 = tid & 3;
    const uint32_t smb = s2u(sm);

    // ldmatrix lane-dependent byte offsets
    const uint32_t aoff0 = (uint32_t)(((wm * 32 + (lane & 15)) * LDAF + ((lane & 16) ? 4 : 0)) * 4);
    const uint32_t aoff1 = aoff0 + 16u * LDAF * 4u;
    uint32_t boff[4];
    #pragma unroll
    for (int j = 0; j < 4; j++)
        boff[j] = (uint32_t)(((wn * 64 + j * 16 + (lane & 7) + ((lane & 16) ? 8 : 0)) * LDB
                              + ((lane & 8) ? 4 : 0)) * 4);

    float acc[2][8][4];
    #pragma unroll
    for (int mt = 0; mt < 2; mt++)
        #pragma unroll
        for (int nt = 0; nt < 8; nt++)
            #pragma unroll
            for (int e = 0; e < 4; e++) acc[mt][nt][e] = 0.f;

    // ---- prologue (R5-style pipeline) ----
    unsigned aCur[4], aPre[4];
    CPB(0);
    LDA_G(0, aCur);
    STA_RES(0, aCur);
    LDA_G(1, aPre);
    asm volatile("cp.async.wait_group 0;" ::: "memory");
    __syncthreads();

    // ---- mainloop ----
    #pragma unroll 2
    for (int u = 0; u < NSTAGE; u++) {
        const int buf = u & 1;
        if (u < NSTAGE - 1) CPB(u + 1);

        const uint32_t bbase = smb + (BBASE_W + (uint32_t)buf * 5120u) * 4u;
        const uint32_t au    = (uint32_t)u * 64u;     // stage column offset in A (bytes)

        #pragma unroll
        for (int kk = 0; kk < 2; kk++) {
            const uint32_t ko  = (uint32_t)kk * 32u;
            unsigned af[2][4];
            ldmat4(af[0], smb + aoff0 + au + ko);
            ldmat4(af[1], smb + aoff1 + au + ko);
            #pragma unroll
            for (int j = 0; j < 4; j++) {
                unsigned bf[4];
                ldmat4(bf, bbase + boff[j] + ko);
                #pragma unroll
                for (int mt = 0; mt < 2; mt++) {
                    mma_f16(acc[mt][2*j][0],   acc[mt][2*j][1],   acc[mt][2*j][2],   acc[mt][2*j][3],
                            af[mt][0], af[mt][1], af[mt][2], af[mt][3], bf[0], bf[1]);
                    mma_f16(acc[mt][2*j+1][0], acc[mt][2*j+1][1], acc[mt][2*j+1][2], acc[mt][2*j+1][3],
                            af[mt][0], af[mt][1], af[mt][2], af[mt][3], bf[2], bf[3]);
                }
            }
        }

        if (u < NSTAGE - 1) STA_RES(u + 1, aPre);
        if (u < NSTAGE - 2) LDA_G(u + 2, aPre);
        if (u < NSTAGE - 1) asm volatile("cp.async.wait_group 0;" ::: "memory");
        __syncthreads();
    }

    // ---- epilogue 1: logits (tanh + v-dot, deterministic staged reduction) ----
    float pe[2][2] = {{0.f, 0.f}, {0.f, 0.f}};
    #pragma unroll
    for (int mt = 0; mt < 2; mt++) {
        #pragma unroll
        for (int nt = 0; nt < 8; nt++) {
            int cb2 = wn * 64 + nt * 8 + 2 * t4;
            float add0 = comb[cb2],     add1 = comb[cb2 + 1];
            float vv0  = vsh[cb2],      vv1  = vsh[cb2 + 1];
            pe[mt][0] += tanhf(acc[mt][nt][0] + add0) * vv0
                       + tanhf(acc[mt][nt][1] + add1) * vv1;
            pe[mt][1] += tanhf(acc[mt][nt][2] + add0) * vv0
                       + tanhf(acc[mt][nt][3] + add1) * vv1;
        }
    }
    #pragma unroll
    for (int mt = 0; mt < 2; mt++) {
        #pragma unroll
        for (int h = 0; h < 2; h++) {
            pe[mt][h] += __shfl_xor_sync(0xffffffffu, pe[mt][h], 1);
            pe[mt][h] += __shfl_xor_sync(0xffffffffu, pe[mt][h], 2);
        }
    }
    if (t4 == 0) {
        #pragma unroll
        for (int mt = 0; mt < 2; mt++) {
            int r0 = wm * 32 + mt * 16 + g;
            part[wn * 128 + r0]     = pe[mt][0];
            part[wn * 128 + r0 + 8] = pe[mt][1];
        }
    }
    __syncthreads();
    if (tid < 128) {
        float l = part[tid] + part[128 + tid] + part[256 + tid] + part[384 + tid];
        g_logits[b * TT + t0 + tid] = l;
        lg[tid] = l;
    }
    __syncthreads();

    // ---- epilogue 2: tile-local max / exp / expsum ----
    if (warp == 0) {
        float m = fmaxf(fmaxf(lg[lane], lg[lane + 32]), fmaxf(lg[lane + 64], lg[lane + 96]));
        #pragma unroll
        for (int o = 16; o > 0; o >>= 1) m = fmaxf(m, __shfl_xor_sync(0xffffffffu, m, o));
        if (lane == 0) scal[0] = m;
    }
    __syncthreads();
    const float mc = scal[0];
    if (tid < 128) ew[tid] = expf(lg[tid] - mc);
    __syncthreads();
    if (warp == 0) {
        float s = (ew[lane] + ew[lane + 32]) + (ew[lane + 64] + ew[lane + 96]);
        #pragma unroll
        for (int o = 16; o > 0; o >>= 1) s += __shfl_xor_sync(0xffffffffu, s, o);
        if (lane == 0) {
            g_ms[(b * NTILE + blockIdx.x) * 2 + 0] = mc;
            g_ms[(b * NTILE + blockIdx.x) * 2 + 1] = s;
        }
    }

    // ---- epilogue 3: partial weighted sum pnum[h] = sum_t ew[t] * A_f16[t,h] ----
    const int hp  = tid & 255;     // h-pair index (word)
    const int seg = tid >> 8;      // token segment 0/1 (64 tokens each)
    float2 pa = make_float2(0.f, 0.f);
    #pragma unroll 8
    for (int t = seg * 64; t < seg * 64 + 64; t++) {
        unsigned w = smw[t * LDAF + hp];
        float2 f = __half22float2(*reinterpret_cast<__half2*>(&w));
        float e = ew[t];
        pa.x = fmaf(f.x, e, pa.x);
        pa.y = fmaf(f.y, e, pa.y);
    }
    pn[seg * 512 + hp * 2]     = pa.x;
    pn[seg * 512 + hp * 2 + 1] = pa.y;
    __syncthreads();
    if (tid < 256) {
        float x0 = pn[tid * 2]     + pn[512 + tid * 2];
        float x1 = pn[tid * 2 + 1] + pn[512 + tid * 2 + 1];
        *reinterpret_cast<float2*>(
            &g_pnum[((size_t)(b * NTILE + blockIdx.x)) * HH + tid * 2]) = make_float2(x0, x1);
    }
}

// ================= Kernel F: finalize — combine tiles, write output + alphas =================
// grid (BB, 2), 256 threads: block y handles h[y*256, y*256+256) and t[y*512, y*512+512)
__global__ __launch_bounds__(256) void finalize_kernel(
    float* __restrict__ out, float* __restrict__ alphas)
{
    __shared__ float ms[2 * NTILE];
    const int b   = blockIdx.x;
    const int hy  = blockIdx.y;
    const int tid = threadIdx.x;

    if (tid < 2 * NTILE) ms[tid] = g_ms[b * 2 * NTILE + tid];
    __syncthreads();

    float M = ms[0];
    #pragma unroll
    for (int c = 1; c < NTILE; c++) M = fmaxf(M, ms[2 * c]);
    float w[NTILE];
    float Z = 0.f;
    #pragma unroll
    for (int c = 0; c < NTILE; c++) {
        w[c] = expf(ms[2 * c] - M);
        Z += ms[2 * c + 1] * w[c];
    }
    const float invZ = 1.0f / Z;

    // output (256 h per block)
    const int h = hy * 256 + tid;
    float o = 0.f;
    #pragma unroll
    for (int c = 0; c < NTILE; c++)
        o += g_pnum[((size_t)(b * NTILE + c)) * HH + h] * w[c];
    out[b * HH + h] = o * invZ;

    // alphas (512 t per block, 2 per thread)
    #pragma unroll
    for (int k = 0; k < 2; k++) {
        int t = hy * 512 + tid + k * 256;
        alphas[b * TT + t] = expf(g_logits[b * TT + t] - M) * invZ;
    }
}

// ================= launch =================
extern "C" void kernel_launch(void* const* d_in, const int* in_sizes, int n_in,
                              void* d_out, int out_size)
{
    const float* genes   = (const float*)d_in[0];   // [B, G]
    const float* smiles  = (const float*)d_in[1];   // [B, T, H]
    const float* w_num   = (const float*)d_in[2];   // [1]
    const float* w_genes = (const float*)d_in[3];   // [G, A]
    const float* b_genes = (const float*)d_in[4];   // [A]
    const float* dkernel = (const float*)d_in[5];   // [H, A]
    const float* dbias   = (const float*)d_in[6];   // [A]
    const float* vvec    = (const float*)d_in[7];   // [A]

    float* out    = (float*)d_out;                  // [B, H] at offset 0
    float* alphas = out + BB * HH;                  // [B, T] after output

    cudaFuncSetAttribute(attn_logits_flash, cudaFuncAttributeMaxDynamicSharedMemorySize, SMEM_BYTES);

    gene_and_prep<<<dim3(BB / BROWS, GSPLIT + 1), 256>>>(genes, w_genes, dkernel);
    attn_logits_flash<<<dim3(NTILE, BB), 512, SMEM_BYTES>>>(smiles, w_num, b_genes, dbias, vvec);
    finalize_kernel<<<dim3(BB, 2), 256>>>(out, alphas);
}

// round 17
// speedup vs baseline: 1.0343x; 1.0343x over previous
#include <cuda_runtime.h>
#include <cuda_fp16.h>
#include <stdint.h>
#include <math.h>

// Problem dims (fixed by reference)
#define BB   128          // batch
#define TT   1024         // tokens
#define HH   512          // hidden
#define AA   256          // attention dim
#define GG   2128         // genes

#define NSTAGE 16         // K stages
#define KC     32         // K per stage
#define LDAF   260        // A smem row stride in b32 words (256 data + 4 pad)
#define LDB    20         // B smem row stride in b32 words
#define NTILE  (TT / 128) // 8 token tiles per batch
#define GSPLIT 28
#define GCHUNK 76         // GG / 28

// smem word layout for attn kernel:
//   A resident: [0, 128*260) = [0, 33280)
//   Bs[buf] at 33280 + buf*5120, buf=0,1 -> ends 43520
//   comb @43520, v @43776, part @44032 (4x128) -> 44544
//   lg @44544 (128), ew @44672 (128), scal @44800 (4), pn @44816 (1024)
#define BBASE_W 33280u
#define COMB_W  43520u
#define VSH_W   43776u
#define PART_W  44032u
#define LG_W    44544u
#define EW_W    44672u
#define SCAL_W  44800u
#define PN_W    44816u
#define SMEM_BYTES ((PN_W + 1024u) * 4u)   // 183360 B

// ---------------- scratch (no cudaMalloc allowed) ----------------
__device__ float    g_gp_part[GSPLIT * BB * AA];     // gene partials
__device__ float    g_logits[BB * TT];               // pre-softmax energies
__device__ __align__(16) unsigned g_bh[NSTAGE * AA * (KC / 2)]; // dkernel^T fp16
__device__ float    g_ms[BB * NTILE * 2];            // per-tile (max, expsum)
__device__ float    g_pnum[BB * NTILE * HH];         // per-tile weighted-sum numerators

// ---------------- helpers ----------------
__device__ __forceinline__ unsigned packh2(float a, float b) {
    __half2 h = __floats2half2_rn(a, b);              // low = a, high = b
    return *reinterpret_cast<unsigned*>(&h);
}
__device__ __forceinline__ uint32_t s2u(const void* p) {
    uint32_t a;
    asm("{ .reg .u64 t; cvta.to.shared.u64 t, %1; cvt.u32.u64 %0, t; }" : "=r"(a) : "l"(p));
    return a;
}
__device__ __forceinline__ void cp16(uint32_t d, const void* s) {
    asm volatile("cp.async.cg.shared.global [%0], [%1], 16;" :: "r"(d), "l"(s) : "memory");
}
__device__ __forceinline__ void ldmat4(unsigned* r, uint32_t addr) {
    asm volatile("ldmatrix.sync.aligned.m8n8.x4.shared.b16 {%0,%1,%2,%3}, [%4];"
                 : "=r"(r[0]), "=r"(r[1]), "=r"(r[2]), "=r"(r[3]) : "r"(addr));
}
__device__ __forceinline__ void mma_f16(float& d0, float& d1, float& d2, float& d3,
                                        unsigned a0, unsigned a1, unsigned a2, unsigned a3,
                                        unsigned b0, unsigned b1) {
    asm volatile(
        "mma.sync.aligned.m16n8k16.row.col.f32.f16.f16.f32 "
        "{%0,%1,%2,%3}, {%4,%5,%6,%7}, {%8,%9}, {%0,%1,%2,%3};\n"
        : "+f"(d0), "+f"(d1), "+f"(d2), "+f"(d3)
        : "r"(a0), "r"(a1), "r"(a2), "r"(a3), "r"(b0), "r"(b1));
}

// ================= Kernel A: gene partials (y<28, 4 b-rows/CTA) + B prep (y==28) =================
__global__ __launch_bounds__(256) void gene_and_prep(
    const float* __restrict__ genes,
    const float* __restrict__ w_genes,
    const float* __restrict__ dk)
{
    const int tid = threadIdx.x;

    if (blockIdx.y == GSPLIT) {
        // ---- prep B: dkernel^T -> fp16, stage-blocked (x = stage, 16 of 32 blocks) ----
        if (blockIdx.x >= NSTAGE) return;
        const int s = blockIdx.x;
        const int a = tid;
        unsigned w[16];
        #pragma unroll
        for (int j = 0; j < 16; j++) {
            float f0 = dk[(size_t)(s * KC + 2 * j)     * AA + a];
            float f1 = dk[(size_t)(s * KC + 2 * j + 1) * AA + a];
            w[j] = packh2(f0, f1);
        }
        uint4* dst = reinterpret_cast<uint4*>(g_bh + ((size_t)s * AA + a) * 16);
        dst[0] = make_uint4(w[0],  w[1],  w[2],  w[3]);
        dst[1] = make_uint4(w[4],  w[5],  w[6],  w[7]);
        dst[2] = make_uint4(w[8],  w[9],  w[10], w[11]);
        dst[3] = make_uint4(w[12], w[13], w[14], w[15]);
        return;
    }

    // ---- gene projection partials (G split 28-way, 4 b-rows, MLP 8) ----
    __shared__ __align__(16) float gs[4 * GCHUNK];   // transposed: gs[g*4 + bb]
    const int b0  = blockIdx.x * 4;
    const int g0  = blockIdx.y * GCHUNK;

    for (int idx = tid; idx < 4 * GCHUNK; idx += 256) {
        int bb = idx / GCHUNK;
        int g  = idx - bb * GCHUNK;
        gs[g * 4 + bb] = genes[(b0 + bb) * GG + g0 + g];
    }
    __syncthreads();

    const int a = tid;
    const float* wp = w_genes + (size_t)g0 * AA + a;
    float acc0 = 0.f, acc1 = 0.f, acc2 = 0.f, acc3 = 0.f;

    int g = 0;
    #pragma unroll 1
    for (; g + 8 <= GCHUNK; g += 8) {
        float w[8];
        #pragma unroll
        for (int k = 0; k < 8; k++) w[k] = __ldg(wp + (size_t)(g + k) * AA);
        #pragma unroll
        for (int k = 0; k < 8; k++) {
            float4 gv = *reinterpret_cast<const float4*>(&gs[(g + k) * 4]);
            acc0 = fmaf(gv.x, w[k], acc0);
            acc1 = fmaf(gv.y, w[k], acc1);
            acc2 = fmaf(gv.z, w[k], acc2);
            acc3 = fmaf(gv.w, w[k], acc3);
        }
    }
    for (; g < GCHUNK; g++) {
        float w = __ldg(wp + (size_t)g * AA);
        float4 gv = *reinterpret_cast<const float4*>(&gs[g * 4]);
        acc0 = fmaf(gv.x, w, acc0);
        acc1 = fmaf(gv.y, w, acc1);
        acc2 = fmaf(gv.z, w, acc2);
        acc3 = fmaf(gv.w, w, acc3);
    }
    float* dst = g_gp_part + ((size_t)blockIdx.y * BB + b0) * AA + a;
    dst[0 * AA] = acc0;
    dst[1 * AA] = acc1;
    dst[2 * AA] = acc2;
    dst[3 * AA] = acc3;
}

// ================= Kernel B: logits + flash epilogue; A-resident, pipelined fill =================
#define CPB(u) do {                                                              \
    int _buf = (u) & 1;                                                          \
    const char* _s = (const char*)g_bh + (size_t)(u) * 16384;                    \
    uint32_t _d = smb + (BBASE_W + (unsigned)_buf * 5120u) * 4u;                 \
    _Pragma("unroll")                                                            \
    for (int _i = 0; _i < 2; _i++) {                                             \
        int _q = tid + _i * 512;                                                 \
        int _row = _q >> 2, _c = _q & 3;                                         \
        cp16(_d + _row * 80 + _c * 16, _s + _row * 64 + _c * 16);                \
    }                                                                            \
    asm volatile("cp.async.commit_group;" ::: "memory");                         \
} while (0)

#define LDA_G(u, dst) do {                                                       \
    const float* _p = Ag + (size_t)r * HH + (u) * KC + c4 * 8;                   \
    float4 _f0 = *(const float4*)_p;                                             \
    float4 _f1 = *(const float4*)(_p + 4);                                       \
    dst[0] = packh2(_f0.x, _f0.y); dst[1] = packh2(_f0.z, _f0.w);                \
    dst[2] = packh2(_f1.x, _f1.y); dst[3] = packh2(_f1.z, _f1.w);                \
} while (0)

#define STA_RES(u, src) do {                                                     \
    unsigned* _d = smw + r * LDAF + (u) * 16 + c4 * 4;                           \
    *(uint4*)_d = make_uint4(src[0], src[1], src[2], src[3]);                    \
} while (0)

__global__ __launch_bounds__(512, 1) void attn_logits_flash(
    const float* __restrict__ smiles,
    const float* __restrict__ w_num,
    const float* __restrict__ b_genes,
    const float* __restrict__ dbias,
    const float* __restrict__ vvec)
{
    extern __shared__ __align__(16) float sm[];
    unsigned* smw  = (unsigned*)sm;
    float*    comb = sm + COMB_W;
    float*    vsh  = sm + VSH_W;
    float*    part = sm + PART_W;
    float*    lg   = sm + LG_W;
    float*    ew   = sm + EW_W;
    float*    scal = sm + SCAL_W;
    float*    pn   = sm + PN_W;

    const int tid  = threadIdx.x;
    const int lane = tid & 31;
    const int warp = tid >> 5;
    const int g    = lane >> 2;
    const int t4   = lane & 3;
    const int wm   = warp & 3;
    const int wn   = warp >> 2;
    const int b    = blockIdx.y;
    const int t0   = blockIdx.x * 128;

    // fused gene_proj reduce: comb = sum(partials)*w_num + b_genes + dbias
    if (tid < AA) {
        float s = 0.f;
        #pragma unroll
        for (int c = 0; c < GSPLIT; c++) s += g_gp_part[((size_t)c * BB + b) * AA + tid];
        comb[tid] = s * w_num[0] + b_genes[tid] + dbias[tid];
        vsh[tid]  = vvec[tid];
    }

    const float* Ag = smiles + ((size_t)b * TT + t0) * HH;
    const int r  = tid >> 2;          // 0..127 (token row)
    const int c4 = tid & 3;
    const uint32_t smb = s2u(sm);

    // ldmatrix lane-dependent byte offsets
    const uint32_t aoff0 = (uint32_t)(((wm * 32 + (lane & 15)) * LDAF + ((lane & 16) ? 4 : 0)) * 4);
    const uint32_t aoff1 = aoff0 + 16u * LDAF * 4u;
    uint32_t boff[4];
    #pragma unroll
    for (int j = 0; j < 4; j++)
        boff[j] = (uint32_t)(((wn * 64 + j * 16 + (lane & 7) + ((lane & 16) ? 8 : 0)) * LDB
                              + ((lane & 8) ? 4 : 0)) * 4);

    float acc[2][8][4];
    #pragma unroll
    for (int mt = 0; mt < 2; mt++)
        #pragma unroll
        for (int nt = 0; nt < 8; nt++)
            #pragma unroll
            for (int e = 0; e < 4; e++) acc[mt][nt][e] = 0.f;

    // ---- prologue (R5-style pipeline) ----
    unsigned aCur[4], aPre[4];
    CPB(0);
    LDA_G(0, aCur);
    STA_RES(0, aCur);
    LDA_G(1, aPre);
    asm volatile("cp.async.wait_group 0;" ::: "memory");
    __syncthreads();

    // ---- mainloop ----
    #pragma unroll 2
    for (int u = 0; u < NSTAGE; u++) {
        const int buf = u & 1;
        if (u < NSTAGE - 1) CPB(u + 1);

        const uint32_t bbase = smb + (BBASE_W + (uint32_t)buf * 5120u) * 4u;
        const uint32_t au    = (uint32_t)u * 64u;     // stage column offset in A (bytes)

        #pragma unroll
        for (int kk = 0; kk < 2; kk++) {
            const uint32_t ko  = (uint32_t)kk * 32u;
            unsigned af[2][4];
            ldmat4(af[0], smb + aoff0 + au + ko);
            ldmat4(af[1], smb + aoff1 + au + ko);
            #pragma unroll
            for (int j = 0; j < 4; j++) {
                unsigned bf[4];
                ldmat4(bf, bbase + boff[j] + ko);
                #pragma unroll
                for (int mt = 0; mt < 2; mt++) {
                    mma_f16(acc[mt][2*j][0],   acc[mt][2*j][1],   acc[mt][2*j][2],   acc[mt][2*j][3],
                            af[mt][0], af[mt][1], af[mt][2], af[mt][3], bf[0], bf[1]);
                    mma_f16(acc[mt][2*j+1][0], acc[mt][2*j+1][1], acc[mt][2*j+1][2], acc[mt][2*j+1][3],
                            af[mt][0], af[mt][1], af[mt][2], af[mt][3], bf[2], bf[3]);
                }
            }
        }

        if (u < NSTAGE - 1) STA_RES(u + 1, aPre);
        if (u < NSTAGE - 2) LDA_G(u + 2, aPre);
        if (u < NSTAGE - 1) asm volatile("cp.async.wait_group 0;" ::: "memory");
        __syncthreads();
    }

    // ---- epilogue 1: logits (tanh + v-dot, deterministic staged reduction) ----
    float pe[2][2] = {{0.f, 0.f}, {0.f, 0.f}};
    #pragma unroll
    for (int mt = 0; mt < 2; mt++) {
        #pragma unroll
        for (int nt = 0; nt < 8; nt++) {
            int cb2 = wn * 64 + nt * 8 + 2 * t4;
            float add0 = comb[cb2],     add1 = comb[cb2 + 1];
            float vv0  = vsh[cb2],      vv1  = vsh[cb2 + 1];
            pe[mt][0] += tanhf(acc[mt][nt][0] + add0) * vv0
                       + tanhf(acc[mt][nt][1] + add1) * vv1;
            pe[mt][1] += tanhf(acc[mt][nt][2] + add0) * vv0
                       + tanhf(acc[mt][nt][3] + add1) * vv1;
        }
    }
    #pragma unroll
    for (int mt = 0; mt < 2; mt++) {
        #pragma unroll
        for (int h = 0; h < 2; h++) {
            pe[mt][h] += __shfl_xor_sync(0xffffffffu, pe[mt][h], 1);
            pe[mt][h] += __shfl_xor_sync(0xffffffffu, pe[mt][h], 2);
        }
    }
    if (t4 == 0) {
        #pragma unroll
        for (int mt = 0; mt < 2; mt++) {
            int r0 = wm * 32 + mt * 16 + g;
            part[wn * 128 + r0]     = pe[mt][0];
            part[wn * 128 + r0 + 8] = pe[mt][1];
        }
    }
    __syncthreads();
    if (tid < 128) {
        float l = part[tid] + part[128 + tid] + part[256 + tid] + part[384 + tid];
        g_logits[b * TT + t0 + tid] = l;
        lg[tid] = l;
    }
    __syncthreads();

    // ---- epilogue 2: tile-local max / exp / expsum ----
    if (warp == 0) {
        float m = fmaxf(fmaxf(lg[lane], lg[lane + 32]), fmaxf(lg[lane + 64], lg[lane + 96]));
        #pragma unroll
        for (int o = 16; o > 0; o >>= 1) m = fmaxf(m, __shfl_xor_sync(0xffffffffu, m, o));
        if (lane == 0) scal[0] = m;
    }
    __syncthreads();
    const float mc = scal[0];
    if (tid < 128) ew[tid] = expf(lg[tid] - mc);
    __syncthreads();
    if (warp == 0) {
        float s = (ew[lane] + ew[lane + 32]) + (ew[lane + 64] + ew[lane + 96]);
        #pragma unroll
        for (int o = 16; o > 0; o >>= 1) s += __shfl_xor_sync(0xffffffffu, s, o);
        if (lane == 0) {
            g_ms[(b * NTILE + blockIdx.x) * 2 + 0] = mc;
            g_ms[(b * NTILE + blockIdx.x) * 2 + 1] = s;
        }
    }

    // ---- epilogue 3: partial weighted sum pnum[h] = sum_t ew[t] * A_f16[t,h] ----
    const int hp  = tid & 255;     // h-pair index (word)
    const int seg = tid >> 8;      // token segment 0/1 (64 tokens each)
    float2 pa = make_float2(0.f, 0.f);
    #pragma unroll 8
    for (int t = seg * 64; t < seg * 64 + 64; t++) {
        unsigned w = smw[t * LDAF + hp];
        float2 f = __half22float2(*reinterpret_cast<__half2*>(&w));
        float e = ew[t];
        pa.x = fmaf(f.x, e, pa.x);
        pa.y = fmaf(f.y, e, pa.y);
    }
    pn[seg * 512 + hp * 2]     = pa.x;
    pn[seg * 512 + hp * 2 + 1] = pa.y;
    __syncthreads();
    if (tid < 256) {
        float x0 = pn[tid * 2]     + pn[512 + tid * 2];
        float x1 = pn[tid * 2 + 1] + pn[512 + tid * 2 + 1];
        *reinterpret_cast<float2*>(
            &g_pnum[((size_t)(b * NTILE + blockIdx.x)) * HH + tid * 2]) = make_float2(x0, x1);
    }
}

// ================= Kernel F: finalize — combine tiles, write output + alphas =================
// grid (BB, 2), 256 threads: block y handles h[y*256, y*256+256) and t[y*512, y*512+512)
__global__ __launch_bounds__(256) void finalize_kernel(
    float* __restrict__ out, float* __restrict__ alphas)
{
    __shared__ float ms[2 * NTILE];
    const int b   = blockIdx.x;
    const int hy  = blockIdx.y;
    const int tid = threadIdx.x;

    if (tid < 2 * NTILE) ms[tid] = g_ms[b * 2 * NTILE + tid];
    __syncthreads();

    float M = ms[0];
    #pragma unroll
    for (int c = 1; c < NTILE; c++) M = fmaxf(M, ms[2 * c]);
    float w[NTILE];
    float Z = 0.f;
    #pragma unroll
    for (int c = 0; c < NTILE; c++) {
        w[c] = expf(ms[2 * c] - M);
        Z += ms[2 * c + 1] * w[c];
    }
    const float invZ = 1.0f / Z;

    // output (256 h per block)
    const int h = hy * 256 + tid;
    float o = 0.f;
    #pragma unroll
    for (int c = 0; c < NTILE; c++)
        o += g_pnum[((size_t)(b * NTILE + c)) * HH + h] * w[c];
    out[b * HH + h] = o * invZ;

    // alphas (512 t per block, 2 per thread)
    #pragma unroll
    for (int k = 0; k < 2; k++) {
        int t = hy * 512 + tid + k * 256;
        alphas[b * TT + t] = expf(g_logits[b * TT + t] - M) * invZ;
    }
}

// ================= launch =================
extern "C" void kernel_launch(void* const* d_in, const int* in_sizes, int n_in,
                              void* d_out, int out_size)
{
    const float* genes   = (const float*)d_in[0];   // [B, G]
    const float* smiles  = (const float*)d_in[1];   // [B, T, H]
    const float* w_num   = (const float*)d_in[2];   // [1]
    const float* w_genes = (const float*)d_in[3];   // [G, A]
    const float* b_genes = (const float*)d_in[4];   // [A]
    const float* dkernel = (const float*)d_in[5];   // [H, A]
    const float* dbias   = (const float*)d_in[6];   // [A]
    const float* vvec    = (const float*)d_in[7];   // [A]

    float* out    = (float*)d_out;                  // [B, H] at offset 0
    float* alphas = out + BB * HH;                  // [B, T] after output

    cudaFuncSetAttribute(attn_logits_flash, cudaFuncAttributeMaxDynamicSharedMemorySize, SMEM_BYTES);

    gene_and_prep<<<dim3(32, GSPLIT + 1), 256>>>(genes, w_genes, dkernel);
    attn_logits_flash<<<dim3(NTILE, BB), 512, SMEM_BYTES>>>(smiles, w_num, b_genes, dbias, vvec);
    finalize_kernel<<<dim3(BB, 2), 256>>>(out, alphas);
}